// round 8
// baseline (speedup 1.0000x reference)
#include <cuda_runtime.h>
#include <cuda_fp16.h>
#include <cstdint>

#define B_   4
#define N_   50000
#define F_   64
#define E_   800000
#define ROWS_TOTAL (B_ * N_)          // 200000
#define E2_  (2 * E_)                 // 1600000

// ---------------------------------------------------------------------------
// Static device scratch
// ---------------------------------------------------------------------------
// pre-activations in fp16, [support][b*N+n][32 half2]  (51.2 MB total)
__device__ __half2 g_preh[2ull * ROWS_TOTAL * 32];
__device__ int     g_count[N_];       // COMBINED per-row degree (both supports)
__device__ int     g_cursor[N_];
__device__ int     g_offs[N_];
__device__ int     g_btot[128];
__device__ int2    g_csr[E2_];        // packed (cidx = s*ROWS_TOTAL + col, val bits)

// ---------------------------------------------------------------------------
// zero counters
// ---------------------------------------------------------------------------
__global__ void zero_kernel() {
    int i = blockIdx.x * blockDim.x + threadIdx.x;
    if (i < N_) { g_count[i] = 0; g_cursor[i] = 0; }
}

// ---------------------------------------------------------------------------
// histogram of destination rows, both supports -> one combined counter set
// ---------------------------------------------------------------------------
__global__ __launch_bounds__(256) void hist_kernel(const int* __restrict__ rows1,
                                                   const int* __restrict__ rows2) {
    int t = blockIdx.x * blockDim.x + threadIdx.x;
    if (t >= E2_) return;
    int r = (t < E_) ? __ldg(rows1 + t) : __ldg(rows2 + (t - E_));
    atomicAdd(&g_count[r], 1);
}

// ---------------------------------------------------------------------------
// exclusive scan of g_count (50000 ints) -> g_offs, 2-level (R3 structure)
// ---------------------------------------------------------------------------
__global__ __launch_bounds__(256) void scan_blocks_kernel() {
    __shared__ int sm[256];
    int base = blockIdx.x * 1024 + threadIdx.x * 4;
    int v[4];
#pragma unroll
    for (int j = 0; j < 4; j++) v[j] = (base + j < N_) ? g_count[base + j] : 0;
    int t = v[0] + v[1] + v[2] + v[3];
    sm[threadIdx.x] = t;
    __syncthreads();
#pragma unroll
    for (int off = 1; off < 256; off <<= 1) {
        int add = (threadIdx.x >= off) ? sm[threadIdx.x - off] : 0;
        __syncthreads();
        sm[threadIdx.x] += add;
        __syncthreads();
    }
    int run = sm[threadIdx.x] - t;
#pragma unroll
    for (int j = 0; j < 4; j++) {
        if (base + j < N_) g_offs[base + j] = run;
        run += v[j];
    }
    if (threadIdx.x == 255) g_btot[blockIdx.x] = sm[255];
}

__global__ void scan_tops_kernel(int nblk) {
    __shared__ int sm[128];
    int t = (threadIdx.x < nblk) ? g_btot[threadIdx.x] : 0;
    sm[threadIdx.x] = t;
    __syncthreads();
#pragma unroll
    for (int off = 1; off < 128; off <<= 1) {
        int add = (threadIdx.x >= off) ? sm[threadIdx.x - off] : 0;
        __syncthreads();
        sm[threadIdx.x] += add;
        __syncthreads();
    }
    if (threadIdx.x < nblk) g_btot[threadIdx.x] = sm[threadIdx.x] - t;
}

__global__ void scan_apply_kernel() {
    int i = blockIdx.x * blockDim.x + threadIdx.x;
    if (i < N_) g_offs[i] += g_btot[i >> 10];
}

// ---------------------------------------------------------------------------
// scatter edges into the combined CSR (cidx encodes support)
// ---------------------------------------------------------------------------
__global__ __launch_bounds__(256) void fill_kernel(const int* __restrict__ rows1,
                                                   const int* __restrict__ cols1,
                                                   const float* __restrict__ vals1,
                                                   const int* __restrict__ rows2,
                                                   const int* __restrict__ cols2,
                                                   const float* __restrict__ vals2) {
    int t = blockIdx.x * blockDim.x + threadIdx.x;
    if (t >= E2_) return;
    int r, cidx; float v;
    if (t < E_) {
        r    = __ldg(rows1 + t);
        cidx = __ldg(cols1 + t);                 // support 0: base offset 0
        v    = __ldg(vals1 + t);
    } else {
        int e = t - E_;
        r    = __ldg(rows2 + e);
        cidx = ROWS_TOTAL + __ldg(cols2 + e);    // support 1: +ROWS_TOTAL
        v    = __ldg(vals2 + e);
    }
    int slot = g_offs[r] + atomicAdd(&g_cursor[r], 1);
    g_csr[slot] = make_int2(cidx, __float_as_int(v));
}

// ---------------------------------------------------------------------------
// pre1 = x@W1, pre2 = x@W2 with packed fma.rn.f32x2, store fp16 (R3 verbatim).
// ---------------------------------------------------------------------------
__global__ __launch_bounds__(256) void gemm_kernel(const float* __restrict__ x,
                                                   const float* __restrict__ W1,
                                                   const float* __restrict__ W2) {
    __shared__ float W1s[64 * 64];
    __shared__ float W2s[64 * 64];
    __shared__ float xs[64][33];

    int tid = threadIdx.x;
    for (int i = tid; i < 64 * 64; i += 256) {
        W1s[i] = W1[i];
        W2s[i] = W2[i];
    }
    int row0 = blockIdx.x * 32;
    const float4* xg = (const float4*)(x + (size_t)row0 * F_);
    for (int i = tid; i < 512; i += 256) {
        float4 v = xg[i];
        int r = i >> 4;
        int k = (i & 15) * 4;
        xs[k][r] = v.x; xs[k + 1][r] = v.y; xs[k + 2][r] = v.z; xs[k + 3][r] = v.w;
    }
    __syncthreads();

    int fpair = tid & 31;
    int rg    = tid >> 5;

    unsigned long long a1[4] = {0ull, 0ull, 0ull, 0ull};
    unsigned long long a2[4] = {0ull, 0ull, 0ull, 0ull};

#pragma unroll
    for (int k = 0; k < 64; k++) {
        unsigned long long w1p = *(const unsigned long long*)&W1s[k * 64 + fpair * 2];
        unsigned long long w2p = *(const unsigned long long*)&W2s[k * 64 + fpair * 2];
#pragma unroll
        for (int r = 0; r < 4; r++) {
            float xv = xs[k][rg * 4 + r];
            unsigned long long xp;
            asm("mov.b64 %0, {%1, %1};" : "=l"(xp) : "f"(xv));
            asm("fma.rn.f32x2 %0, %1, %2, %0;" : "+l"(a1[r]) : "l"(xp), "l"(w1p));
            asm("fma.rn.f32x2 %0, %1, %2, %0;" : "+l"(a2[r]) : "l"(xp), "l"(w2p));
        }
    }

    const size_t sup_stride = (size_t)ROWS_TOTAL * 32;
#pragma unroll
    for (int r = 0; r < 4; r++) {
        size_t row = (size_t)(row0 + rg * 4 + r);
        float lo, hi;
        asm("mov.b64 {%0, %1}, %2;" : "=f"(lo), "=f"(hi) : "l"(a1[r]));
        g_preh[row * 32 + fpair] = __floats2half2_rn(lo, hi);
        asm("mov.b64 {%0, %1}, %2;" : "=f"(lo), "=f"(hi) : "l"(a2[r]));
        g_preh[sup_stride + row * 32 + fpair] = __floats2half2_rn(lo, hi);
    }
}

// ---------------------------------------------------------------------------
// Gather SpMM + bias + relu. One warp per output row, all 4 batches,
// ONE combined edge list (support encoded in cidx). Inner per-edge body is
// the proven R3 body (4x LDG.32 + 8 FMA).
// ---------------------------------------------------------------------------
__global__ __launch_bounds__(256) void gather_kernel(const float* __restrict__ bias,
                                                     float* __restrict__ out) {
    int row  = (blockIdx.x * blockDim.x + threadIdx.x) >> 5;
    int lane = threadIdx.x & 31;
    if (row >= N_) return;

    float bx = __ldg(bias + lane * 2);
    float by = __ldg(bias + lane * 2 + 1);
    float2 acc[4];
#pragma unroll
    for (int b = 0; b < 4; b++) acc[b] = make_float2(bx, by);

    const size_t bstride = (size_t)N_ * 32;   // half2 stride per batch

    int start = g_offs[row];
    int deg   = g_count[row];

    for (int c0 = 0; c0 < deg; c0 += 32) {
        int nc = min(32, deg - c0);
        int2 cv = make_int2(0, 0);
        if (lane < nc) cv = __ldg(g_csr + start + c0 + lane);
        for (int i = 0; i < nc; i++) {
            int   ci = __shfl_sync(0xffffffffu, cv.x, i);
            float vi = __int_as_float(__shfl_sync(0xffffffffu, cv.y, i));
            const __half2* src = g_preh + (size_t)ci * 32 + lane;
#pragma unroll
            for (int b = 0; b < 4; b++) {
                float2 f = __half22float2(__ldg(src + (size_t)b * bstride));
                acc[b].x = fmaf(vi, f.x, acc[b].x);
                acc[b].y = fmaf(vi, f.y, acc[b].y);
            }
        }
    }

    float2* outv = (float2*)out;
#pragma unroll
    for (int b = 0; b < 4; b++) {
        float2 o;
        o.x = fmaxf(acc[b].x, 0.f);
        o.y = fmaxf(acc[b].y, 0.f);
        outv[((size_t)b * N_ + row) * 32 + lane] = o;
    }
}

extern "C" void kernel_launch(void* const* d_in, const int* in_sizes, int n_in,
                              void* d_out, int out_size) {
    const float* x     = (const float*)d_in[0];
    const int*   rows1 = (const int*)  d_in[1];
    const int*   cols1 = (const int*)  d_in[2];
    const float* vals1 = (const float*)d_in[3];
    const int*   rows2 = (const int*)  d_in[4];
    const int*   cols2 = (const int*)  d_in[5];
    const float* vals2 = (const float*)d_in[6];
    const float* W1    = (const float*)d_in[7];
    const float* W2    = (const float*)d_in[8];
    const float* bias  = (const float*)d_in[9];
    float*       out   = (float*)d_out;

    const int nScanBlocks = (N_ + 1023) / 1024;   // 49

    zero_kernel<<<(N_ + 255) / 256, 256>>>();
    hist_kernel<<<(E2_ + 255) / 256, 256>>>(rows1, rows2);
    scan_blocks_kernel<<<nScanBlocks, 256>>>();
    scan_tops_kernel<<<1, 128>>>(nScanBlocks);
    scan_apply_kernel<<<(N_ + 255) / 256, 256>>>();
    fill_kernel<<<(E2_ + 255) / 256, 256>>>(rows1, cols1, vals1, rows2, cols2, vals2);

    gemm_kernel<<<ROWS_TOTAL / 32, 256>>>(x, W1, W2);
    gather_kernel<<<(N_ * 32 + 255) / 256, 256>>>(bias, out);
}

// round 9
// speedup vs baseline: 1.7457x; 1.7457x over previous
#include <cuda_runtime.h>
#include <cuda_fp16.h>
#include <cstdint>

#define B_   4
#define N_   50000
#define F_   64
#define E_   800000
#define ROWS_TOTAL (B_ * N_)          // 200000
#define E2_  (2 * E_)                 // 1600000
#define N2_  (2 * N_)                 // 100000

// ---------------------------------------------------------------------------
// Static device scratch (R3 layout)
// ---------------------------------------------------------------------------
// pre-activations in fp16, [support][b*N+n][32 half2]  (51.2 MB total)
__device__ __half2 g_preh[2ull * ROWS_TOTAL * 32];
__device__ int     g_count[N2_];      // per (support,row) degree
__device__ int     g_cursor[N2_];     // fill cursors
__device__ int     g_offs[N2_];       // exclusive prefix (CSR row offsets)
__device__ int     g_btot[128];       // scan block totals
__device__ int     g_csr_col[E2_];
__device__ float   g_csr_val[E2_];

// ---------------------------------------------------------------------------
// zero counters (R3 verbatim)
// ---------------------------------------------------------------------------
__global__ void zero_kernel() {
    int i = blockIdx.x * blockDim.x + threadIdx.x;
    if (i < N2_) { g_count[i] = 0; g_cursor[i] = 0; }
}

// ---------------------------------------------------------------------------
// histogram of destination rows, both supports (R3 verbatim)
// ---------------------------------------------------------------------------
__global__ __launch_bounds__(256) void hist_kernel(const int* __restrict__ rows1,
                                                   const int* __restrict__ rows2) {
    int t = blockIdx.x * blockDim.x + threadIdx.x;
    if (t >= E2_) return;
    int r = (t < E_) ? __ldg(rows1 + t) : __ldg(rows2 + (t - E_));
    int idx = (t < E_) ? r : (N_ + r);
    atomicAdd(&g_count[idx], 1);
}

// ---------------------------------------------------------------------------
// exclusive scan of g_count (100000 ints) -> g_offs, 2-level (R3 verbatim)
// ---------------------------------------------------------------------------
__global__ __launch_bounds__(256) void scan_blocks_kernel() {
    __shared__ int sm[256];
    int base = blockIdx.x * 1024 + threadIdx.x * 4;
    int v[4];
#pragma unroll
    for (int j = 0; j < 4; j++) v[j] = (base + j < N2_) ? g_count[base + j] : 0;
    int t = v[0] + v[1] + v[2] + v[3];
    sm[threadIdx.x] = t;
    __syncthreads();
#pragma unroll
    for (int off = 1; off < 256; off <<= 1) {
        int add = (threadIdx.x >= off) ? sm[threadIdx.x - off] : 0;
        __syncthreads();
        sm[threadIdx.x] += add;
        __syncthreads();
    }
    int run = sm[threadIdx.x] - t;
#pragma unroll
    for (int j = 0; j < 4; j++) {
        if (base + j < N2_) g_offs[base + j] = run;
        run += v[j];
    }
    if (threadIdx.x == 255) g_btot[blockIdx.x] = sm[255];
}

__global__ void scan_tops_kernel(int nblk) {
    __shared__ int sm[128];
    int t = (threadIdx.x < nblk) ? g_btot[threadIdx.x] : 0;
    sm[threadIdx.x] = t;
    __syncthreads();
#pragma unroll
    for (int off = 1; off < 128; off <<= 1) {
        int add = (threadIdx.x >= off) ? sm[threadIdx.x - off] : 0;
        __syncthreads();
        sm[threadIdx.x] += add;
        __syncthreads();
    }
    if (threadIdx.x < nblk) g_btot[threadIdx.x] = sm[threadIdx.x] - t;
}

__global__ void scan_apply_kernel() {
    int i = blockIdx.x * blockDim.x + threadIdx.x;
    if (i < N2_) g_offs[i] += g_btot[i >> 10];
}

// ---------------------------------------------------------------------------
// scatter edges into CSR slots (R3 verbatim: separate col/val arrays)
// ---------------------------------------------------------------------------
__global__ __launch_bounds__(256) void fill_kernel(const int* __restrict__ rows1,
                                                   const int* __restrict__ cols1,
                                                   const float* __restrict__ vals1,
                                                   const int* __restrict__ rows2,
                                                   const int* __restrict__ cols2,
                                                   const float* __restrict__ vals2) {
    int t = blockIdx.x * blockDim.x + threadIdx.x;
    if (t >= E2_) return;
    int r, c; float v; int idx;
    if (t < E_) {
        r = __ldg(rows1 + t); c = __ldg(cols1 + t); v = __ldg(vals1 + t);
        idx = r;
    } else {
        int e = t - E_;
        r = __ldg(rows2 + e); c = __ldg(cols2 + e); v = __ldg(vals2 + e);
        idx = N_ + r;
    }
    int slot = g_offs[idx] + atomicAdd(&g_cursor[idx], 1);
    g_csr_col[slot] = c;
    g_csr_val[slot] = v;
}

// ---------------------------------------------------------------------------
// NEW: fp16 tensor-core GEMM. pre1 = x@W1, pre2 = x@W2.
// 64 rows/block, 256 threads = 8 warps: warp = (sup = wid>>2, m-tile = wid&3).
// Each warp: m16 x n64 x k64 via 8 n-tiles x 4 k-steps of m16n8k16 HMMA.
// A = x rows (fp16, row-major smem), B = W^T (fp16, [n][k] smem).
// ---------------------------------------------------------------------------
__global__ __launch_bounds__(256) void gemm_kernel(const float* __restrict__ x,
                                                   const float* __restrict__ W1,
                                                   const float* __restrict__ W2) {
    __shared__ __align__(16) __half xh[64][72];      // [row][k], pad 72
    __shared__ __align__(16) __half Wt[2][64][72];   // [sup][n][k]

    int tid = threadIdx.x;
    int row0 = blockIdx.x * 64;

    // load W transposed, fp32 -> fp16
    for (int i = tid; i < 64 * 64; i += 256) {
        int n = i & 63, k = i >> 6;
        Wt[0][n][k] = __float2half(W1[k * 64 + n]);
        Wt[1][n][k] = __float2half(W2[k * 64 + n]);
    }
    // load x tile, fp32 -> fp16
    const float4* xg = (const float4*)(x + (size_t)row0 * F_);
    for (int i = tid; i < 1024; i += 256) {          // 64 rows x 16 float4
        float4 v = xg[i];
        int r = i >> 4, kc = (i & 15) * 4;
        xh[r][kc]     = __float2half(v.x);
        xh[r][kc + 1] = __float2half(v.y);
        xh[r][kc + 2] = __float2half(v.z);
        xh[r][kc + 3] = __float2half(v.w);
    }
    __syncthreads();

    int wid  = tid >> 5, lane = tid & 31;
    int sup  = wid >> 2;           // support 0/1
    int m0   = (wid & 3) * 16;     // m-tile base row
    int g    = lane >> 2;          // groupID 0..7
    int tg   = lane & 3;           // thread-in-group 0..3

    float acc[8][4];
#pragma unroll
    for (int n = 0; n < 8; n++)
#pragma unroll
        for (int j = 0; j < 4; j++) acc[n][j] = 0.f;

#pragma unroll
    for (int ks = 0; ks < 4; ks++) {
        int kb = ks * 16 + tg * 2;
        uint32_t a0 = *(const uint32_t*)&xh[m0 + g][kb];
        uint32_t a1 = *(const uint32_t*)&xh[m0 + g + 8][kb];
        uint32_t a2 = *(const uint32_t*)&xh[m0 + g][kb + 8];
        uint32_t a3 = *(const uint32_t*)&xh[m0 + g + 8][kb + 8];
#pragma unroll
        for (int n = 0; n < 8; n++) {
            uint32_t b0 = *(const uint32_t*)&Wt[sup][n * 8 + g][kb];
            uint32_t b1 = *(const uint32_t*)&Wt[sup][n * 8 + g][kb + 8];
            asm volatile(
                "mma.sync.aligned.m16n8k16.row.col.f32.f16.f16.f32 "
                "{%0,%1,%2,%3}, {%4,%5,%6,%7}, {%8,%9}, {%0,%1,%2,%3};"
                : "+f"(acc[n][0]), "+f"(acc[n][1]), "+f"(acc[n][2]), "+f"(acc[n][3])
                : "r"(a0), "r"(a1), "r"(a2), "r"(a3), "r"(b0), "r"(b1));
        }
    }

    // epilogue: c0,c1 -> row g cols 2tg,2tg+1 of n-tile; c2,c3 -> row g+8.
    const size_t sup_stride = (size_t)ROWS_TOTAL * 32;   // half2 units
    __half2* dst = g_preh + (size_t)sup * sup_stride;
#pragma unroll
    for (int n = 0; n < 8; n++) {
        int fpair = n * 4 + tg;
        size_t r = (size_t)(row0 + m0 + g);
        dst[r * 32 + fpair]       = __floats2half2_rn(acc[n][0], acc[n][1]);
        dst[(r + 8) * 32 + fpair] = __floats2half2_rn(acc[n][2], acc[n][3]);
    }
}

// ---------------------------------------------------------------------------
// Gather SpMM + bias + relu (R3 verbatim). One warp per row, all 4 batches.
// ---------------------------------------------------------------------------
__global__ __launch_bounds__(256) void gather_kernel(const float* __restrict__ bias,
                                                     float* __restrict__ out) {
    int gw   = (blockIdx.x * blockDim.x + threadIdx.x) >> 5;
    int lane = threadIdx.x & 31;
    if (gw >= N_) return;
    int row = gw;

    float bx = __ldg(bias + lane * 2);
    float by = __ldg(bias + lane * 2 + 1);
    float2 acc[4];
#pragma unroll
    for (int b = 0; b < 4; b++) acc[b] = make_float2(bx, by);

    const size_t sup_stride = (size_t)ROWS_TOTAL * 32;
    const size_t bstride    = (size_t)N_ * 32;

#pragma unroll
    for (int s = 0; s < 2; s++) {
        int idx   = s * N_ + row;
        int start = g_offs[idx];
        int deg   = g_count[idx];
        const __half2* pre = g_preh + (size_t)s * sup_stride;

        for (int c0 = 0; c0 < deg; c0 += 32) {
            int nc = min(32, deg - c0);
            int   colv = 0;
            float vv   = 0.f;
            if (lane < nc) {
                colv = g_csr_col[start + c0 + lane];
                vv   = g_csr_val[start + c0 + lane];
            }
            for (int i = 0; i < nc; i++) {
                int   ci = __shfl_sync(0xffffffffu, colv, i);
                float vi = __shfl_sync(0xffffffffu, vv,   i);
                const __half2* src = pre + (size_t)ci * 32 + lane;
#pragma unroll
                for (int b = 0; b < 4; b++) {
                    __half2 h = __ldg(src + (size_t)b * bstride);
                    float2 f = __half22float2(h);
                    acc[b].x = fmaf(vi, f.x, acc[b].x);
                    acc[b].y = fmaf(vi, f.y, acc[b].y);
                }
            }
        }
    }

    float2* outv = (float2*)out;
#pragma unroll
    for (int b = 0; b < 4; b++) {
        float2 o;
        o.x = fmaxf(acc[b].x, 0.f);
        o.y = fmaxf(acc[b].y, 0.f);
        outv[((size_t)b * N_ + row) * 32 + lane] = o;
    }
}

extern "C" void kernel_launch(void* const* d_in, const int* in_sizes, int n_in,
                              void* d_out, int out_size) {
    const float* x     = (const float*)d_in[0];
    const int*   rows1 = (const int*)  d_in[1];
    const int*   cols1 = (const int*)  d_in[2];
    const float* vals1 = (const float*)d_in[3];
    const int*   rows2 = (const int*)  d_in[4];
    const int*   cols2 = (const int*)  d_in[5];
    const float* vals2 = (const float*)d_in[6];
    const float* W1    = (const float*)d_in[7];
    const float* W2    = (const float*)d_in[8];
    const float* bias  = (const float*)d_in[9];
    float*       out   = (float*)d_out;

    const int nScanBlocks = (N2_ + 1023) / 1024;   // 98

    zero_kernel<<<(N2_ + 255) / 256, 256>>>();
    hist_kernel<<<(E2_ + 255) / 256, 256>>>(rows1, rows2);
    scan_blocks_kernel<<<nScanBlocks, 256>>>();
    scan_tops_kernel<<<1, 128>>>(nScanBlocks);
    scan_apply_kernel<<<(N2_ + 255) / 256, 256>>>();
    fill_kernel<<<(E2_ + 255) / 256, 256>>>(rows1, cols1, vals1, rows2, cols2, vals2);

    gemm_kernel<<<ROWS_TOTAL / 64, 256>>>(x, W1, W2);
    gather_kernel<<<(N_ * 32 + 255) / 256, 256>>>(bias, out);
}

// round 10
// speedup vs baseline: 1.7772x; 1.0181x over previous
#include <cuda_runtime.h>
#include <cuda_fp16.h>
#include <cstdint>

#define B_   4
#define N_   50000
#define F_   64
#define E_   800000
#define ROWS_TOTAL (B_ * N_)          // 200000
#define E2_  (2 * E_)                 // 1600000
#define N2_  (2 * N_)                 // 100000

// ---------------------------------------------------------------------------
// Static device scratch (R3 layout)
// ---------------------------------------------------------------------------
// pre-activations in fp16, [support][b*N+n][32 half2]  (51.2 MB total)
__device__ __half2 g_preh[2ull * ROWS_TOTAL * 32];
__device__ int     g_count[N2_];      // per (support,row) degree
__device__ int     g_cursor[N2_];     // fill cursors
__device__ int     g_offs[N2_];       // exclusive prefix (CSR row offsets)
__device__ int     g_btot[128];       // scan block totals
__device__ int     g_csr_col[E2_];
__device__ float   g_csr_val[E2_];

// ---------------------------------------------------------------------------
// zero counters (R3 verbatim)
// ---------------------------------------------------------------------------
__global__ void zero_kernel() {
    int i = blockIdx.x * blockDim.x + threadIdx.x;
    if (i < N2_) { g_count[i] = 0; g_cursor[i] = 0; }
}

// ---------------------------------------------------------------------------
// histogram of destination rows, both supports (R3 verbatim)
// ---------------------------------------------------------------------------
__global__ __launch_bounds__(256) void hist_kernel(const int* __restrict__ rows1,
                                                   const int* __restrict__ rows2) {
    int t = blockIdx.x * blockDim.x + threadIdx.x;
    if (t >= E2_) return;
    int r = (t < E_) ? __ldg(rows1 + t) : __ldg(rows2 + (t - E_));
    int idx = (t < E_) ? r : (N_ + r);
    atomicAdd(&g_count[idx], 1);
}

// ---------------------------------------------------------------------------
// exclusive scan of g_count (100000 ints) -> g_offs, 2-level (R3 verbatim)
// ---------------------------------------------------------------------------
__global__ __launch_bounds__(256) void scan_blocks_kernel() {
    __shared__ int sm[256];
    int base = blockIdx.x * 1024 + threadIdx.x * 4;
    int v[4];
#pragma unroll
    for (int j = 0; j < 4; j++) v[j] = (base + j < N2_) ? g_count[base + j] : 0;
    int t = v[0] + v[1] + v[2] + v[3];
    sm[threadIdx.x] = t;
    __syncthreads();
#pragma unroll
    for (int off = 1; off < 256; off <<= 1) {
        int add = (threadIdx.x >= off) ? sm[threadIdx.x - off] : 0;
        __syncthreads();
        sm[threadIdx.x] += add;
        __syncthreads();
    }
    int run = sm[threadIdx.x] - t;
#pragma unroll
    for (int j = 0; j < 4; j++) {
        if (base + j < N2_) g_offs[base + j] = run;
        run += v[j];
    }
    if (threadIdx.x == 255) g_btot[blockIdx.x] = sm[255];
}

__global__ void scan_tops_kernel(int nblk) {
    __shared__ int sm[128];
    int t = (threadIdx.x < nblk) ? g_btot[threadIdx.x] : 0;
    sm[threadIdx.x] = t;
    __syncthreads();
#pragma unroll
    for (int off = 1; off < 128; off <<= 1) {
        int add = (threadIdx.x >= off) ? sm[threadIdx.x - off] : 0;
        __syncthreads();
        sm[threadIdx.x] += add;
        __syncthreads();
    }
    if (threadIdx.x < nblk) g_btot[threadIdx.x] = sm[threadIdx.x] - t;
}

__global__ void scan_apply_kernel() {
    int i = blockIdx.x * blockDim.x + threadIdx.x;
    if (i < N2_) g_offs[i] += g_btot[i >> 10];
}

// ---------------------------------------------------------------------------
// scatter edges into CSR slots (R3 verbatim)
// ---------------------------------------------------------------------------
__global__ __launch_bounds__(256) void fill_kernel(const int* __restrict__ rows1,
                                                   const int* __restrict__ cols1,
                                                   const float* __restrict__ vals1,
                                                   const int* __restrict__ rows2,
                                                   const int* __restrict__ cols2,
                                                   const float* __restrict__ vals2) {
    int t = blockIdx.x * blockDim.x + threadIdx.x;
    if (t >= E2_) return;
    int r, c; float v; int idx;
    if (t < E_) {
        r = __ldg(rows1 + t); c = __ldg(cols1 + t); v = __ldg(vals1 + t);
        idx = r;
    } else {
        int e = t - E_;
        r = __ldg(rows2 + e); c = __ldg(cols2 + e); v = __ldg(vals2 + e);
        idx = N_ + r;
    }
    int slot = g_offs[idx] + atomicAdd(&g_cursor[idx], 1);
    g_csr_col[slot] = c;
    g_csr_val[slot] = v;
}

// ---------------------------------------------------------------------------
// fp16 tensor-core GEMM (R9 verbatim). pre1 = x@W1, pre2 = x@W2.
// ---------------------------------------------------------------------------
__global__ __launch_bounds__(256) void gemm_kernel(const float* __restrict__ x,
                                                   const float* __restrict__ W1,
                                                   const float* __restrict__ W2) {
    __shared__ __align__(16) __half xh[64][72];      // [row][k], pad 72
    __shared__ __align__(16) __half Wt[2][64][72];   // [sup][n][k]

    int tid = threadIdx.x;
    int row0 = blockIdx.x * 64;

    for (int i = tid; i < 64 * 64; i += 256) {
        int n = i & 63, k = i >> 6;
        Wt[0][n][k] = __float2half(W1[k * 64 + n]);
        Wt[1][n][k] = __float2half(W2[k * 64 + n]);
    }
    const float4* xg = (const float4*)(x + (size_t)row0 * F_);
    for (int i = tid; i < 1024; i += 256) {          // 64 rows x 16 float4
        float4 v = xg[i];
        int r = i >> 4, kc = (i & 15) * 4;
        xh[r][kc]     = __float2half(v.x);
        xh[r][kc + 1] = __float2half(v.y);
        xh[r][kc + 2] = __float2half(v.z);
        xh[r][kc + 3] = __float2half(v.w);
    }
    __syncthreads();

    int wid  = tid >> 5, lane = tid & 31;
    int sup  = wid >> 2;
    int m0   = (wid & 3) * 16;
    int g    = lane >> 2;
    int tg   = lane & 3;

    float acc[8][4];
#pragma unroll
    for (int n = 0; n < 8; n++)
#pragma unroll
        for (int j = 0; j < 4; j++) acc[n][j] = 0.f;

#pragma unroll
    for (int ks = 0; ks < 4; ks++) {
        int kb = ks * 16 + tg * 2;
        uint32_t a0 = *(const uint32_t*)&xh[m0 + g][kb];
        uint32_t a1 = *(const uint32_t*)&xh[m0 + g + 8][kb];
        uint32_t a2 = *(const uint32_t*)&xh[m0 + g][kb + 8];
        uint32_t a3 = *(const uint32_t*)&xh[m0 + g + 8][kb + 8];
#pragma unroll
        for (int n = 0; n < 8; n++) {
            uint32_t b0 = *(const uint32_t*)&Wt[sup][n * 8 + g][kb];
            uint32_t b1 = *(const uint32_t*)&Wt[sup][n * 8 + g][kb + 8];
            asm volatile(
                "mma.sync.aligned.m16n8k16.row.col.f32.f16.f16.f32 "
                "{%0,%1,%2,%3}, {%4,%5,%6,%7}, {%8,%9}, {%0,%1,%2,%3};"
                : "+f"(acc[n][0]), "+f"(acc[n][1]), "+f"(acc[n][2]), "+f"(acc[n][3])
                : "r"(a0), "r"(a1), "r"(a2), "r"(a3), "r"(b0), "r"(b1));
        }
    }

    const size_t sup_stride = (size_t)ROWS_TOTAL * 32;
    __half2* dst = g_preh + (size_t)sup * sup_stride;
#pragma unroll
    for (int n = 0; n < 8; n++) {
        int fpair = n * 4 + tg;
        size_t r = (size_t)(row0 + m0 + g);
        dst[r * 32 + fpair]       = __floats2half2_rn(acc[n][0], acc[n][1]);
        dst[(r + 8) * 32 + fpair] = __floats2half2_rn(acc[n][2], acc[n][3]);
    }
}

// ---------------------------------------------------------------------------
// Gather SpMM + bias + relu (R3 verbatim). One warp per row, all 4 batches.
// ---------------------------------------------------------------------------
__global__ __launch_bounds__(256) void gather_kernel(const float* __restrict__ bias,
                                                     float* __restrict__ out) {
    int gw   = (blockIdx.x * blockDim.x + threadIdx.x) >> 5;
    int lane = threadIdx.x & 31;
    if (gw >= N_) return;
    int row = gw;

    float bx = __ldg(bias + lane * 2);
    float by = __ldg(bias + lane * 2 + 1);
    float2 acc[4];
#pragma unroll
    for (int b = 0; b < 4; b++) acc[b] = make_float2(bx, by);

    const size_t sup_stride = (size_t)ROWS_TOTAL * 32;
    const size_t bstride    = (size_t)N_ * 32;

#pragma unroll
    for (int s = 0; s < 2; s++) {
        int idx   = s * N_ + row;
        int start = g_offs[idx];
        int deg   = g_count[idx];
        const __half2* pre = g_preh + (size_t)s * sup_stride;

        for (int c0 = 0; c0 < deg; c0 += 32) {
            int nc = min(32, deg - c0);
            int   colv = 0;
            float vv   = 0.f;
            if (lane < nc) {
                colv = g_csr_col[start + c0 + lane];
                vv   = g_csr_val[start + c0 + lane];
            }
            for (int i = 0; i < nc; i++) {
                int   ci = __shfl_sync(0xffffffffu, colv, i);
                float vi = __shfl_sync(0xffffffffu, vv,   i);
                const __half2* src = pre + (size_t)ci * 32 + lane;
#pragma unroll
                for (int b = 0; b < 4; b++) {
                    __half2 h = __ldg(src + (size_t)b * bstride);
                    float2 f = __half22float2(h);
                    acc[b].x = fmaf(vi, f.x, acc[b].x);
                    acc[b].y = fmaf(vi, f.y, acc[b].y);
                }
            }
        }
    }

    float2* outv = (float2*)out;
#pragma unroll
    for (int b = 0; b < 4; b++) {
        float2 o;
        o.x = fmaxf(acc[b].x, 0.f);
        o.y = fmaxf(acc[b].y, 0.f);
        outv[((size_t)b * N_ + row) * 32 + lane] = o;
    }
}

extern "C" void kernel_launch(void* const* d_in, const int* in_sizes, int n_in,
                              void* d_out, int out_size) {
    const float* x     = (const float*)d_in[0];
    const int*   rows1 = (const int*)  d_in[1];
    const int*   cols1 = (const int*)  d_in[2];
    const float* vals1 = (const float*)d_in[3];
    const int*   rows2 = (const int*)  d_in[4];
    const int*   cols2 = (const int*)  d_in[5];
    const float* vals2 = (const float*)d_in[6];
    const float* W1    = (const float*)d_in[7];
    const float* W2    = (const float*)d_in[8];
    const float* bias  = (const float*)d_in[9];
    float*       out   = (float*)d_out;

    // Lazily-created side stream + events for the fork/join. Created on the
    // first (eager correctness) call — never during graph capture. The work
    // issued per call is identical every call.
    static cudaStream_t s_side = nullptr;
    static cudaEvent_t  ev_fork = nullptr;
    static cudaEvent_t  ev_join = nullptr;
    if (s_side == nullptr) {
        cudaStreamCreateWithFlags(&s_side, cudaStreamNonBlocking);
        cudaEventCreateWithFlags(&ev_fork, cudaEventDisableTiming);
        cudaEventCreateWithFlags(&ev_join, cudaEventDisableTiming);
    }

    const int nScanBlocks = (N2_ + 1023) / 1024;   // 98

    // ---- fork: gemm runs concurrently with the CSR build ----
    cudaEventRecord(ev_fork, 0);
    cudaStreamWaitEvent(s_side, ev_fork, 0);
    gemm_kernel<<<ROWS_TOTAL / 64, 256, 0, s_side>>>(x, W1, W2);
    cudaEventRecord(ev_join, s_side);

    // ---- main chain: CSR construction ----
    zero_kernel<<<(N2_ + 255) / 256, 256>>>();
    hist_kernel<<<(E2_ + 255) / 256, 256>>>(rows1, rows2);
    scan_blocks_kernel<<<nScanBlocks, 256>>>();
    scan_tops_kernel<<<1, 128>>>(nScanBlocks);
    scan_apply_kernel<<<(N2_ + 255) / 256, 256>>>();
    fill_kernel<<<(E2_ + 255) / 256, 256>>>(rows1, cols1, vals1, rows2, cols2, vals2);

    // ---- join: gather needs both pre-activations and the CSR ----
    cudaStreamWaitEvent(0, ev_join, 0);
    gather_kernel<<<(N_ * 32 + 255) / 256, 256>>>(bias, out);
}